// round 15
// baseline (speedup 1.0000x reference)
#include <cuda_runtime.h>
#include <cuda_fp16.h>
#include <cstdint>

// Problem constants
#define BT_    64000          // B*T
#define FIN_   1024
#define GV_    640            // GROUPS*NUM_VARS
#define NV_    320
#define VD_    128            // VAR_DIM
#define QELEMS (BT_ * 256)    // q output elements

#define TAU_RESCUE 0.02f

// ---------------------------------------------------------------------------
// Device scratch (no cudaMalloc allowed)
// ---------------------------------------------------------------------------
__device__ __align__(16) __half g_wh[(size_t)GV_ * FIN_];
__device__ __align__(16) __half g_wl[(size_t)GV_ * FIN_];
__device__ __align__(16) float  g_logits[(size_t)BT_ * GV_];
__device__ float        g_probsum[GV_];
__device__ unsigned int g_counts[GV_];

// ---------------------------------------------------------------------------
// PTX helpers (base-target only: cp.async / ldmatrix / mma.sync)
// ---------------------------------------------------------------------------
__device__ __forceinline__ uint32_t smem_u32(const void* p) {
    uint32_t a;
    asm("{ .reg .u64 t; cvta.to.shared.u64 t, %1; cvt.u32.u64 %0, t; }" : "=r"(a) : "l"(p));
    return a;
}
__device__ __forceinline__ void cpasync16(uint32_t dst, const void* src) {
    asm volatile("cp.async.cg.shared.global [%0], [%1], 16;" :: "r"(dst), "l"(src));
}
#define CP_COMMIT() asm volatile("cp.async.commit_group;")
#define CP_WAIT1()  asm volatile("cp.async.wait_group 1;")
#define CP_WAIT0()  asm volatile("cp.async.wait_group 0;")

#define LDM4(r, addr) \
    asm volatile("ldmatrix.sync.aligned.m8n8.x4.shared.b16 {%0,%1,%2,%3}, [%4];" \
                 : "=r"((r)[0]), "=r"((r)[1]), "=r"((r)[2]), "=r"((r)[3]) : "r"(addr))

#define MMA16816(d, a, b0r, b1r) \
    asm volatile("mma.sync.aligned.m16n8k16.row.col.f32.f16.f16.f32 " \
                 "{%0,%1,%2,%3},{%4,%5,%6,%7},{%8,%9},{%0,%1,%2,%3};" \
                 : "+f"((d)[0]), "+f"((d)[1]), "+f"((d)[2]), "+f"((d)[3]) \
                 : "r"((a)[0]), "r"((a)[1]), "r"((a)[2]), "r"((a)[3]), "r"(b0r), "r"(b1r))

// ---------------------------------------------------------------------------
// fp16x2 split
// ---------------------------------------------------------------------------
__device__ __forceinline__ void split2(float x, __half& h, __half& l) {
    h = __float2half(x);
    l = __float2half(x - __half2float(h));
}

__global__ __launch_bounds__(256) void wsplit_kernel(const float* __restrict__ W) {
    const size_t base = ((size_t)blockIdx.x * 256 + threadIdx.x) * 8;
    const float4 v0 = *(const float4*)(W + base);
    const float4 v1 = *(const float4*)(W + base + 4);
    const float e[8] = {v0.x, v0.y, v0.z, v0.w, v1.x, v1.y, v1.z, v1.w};
    __half ph[8], pl[8];
#pragma unroll
    for (int i = 0; i < 8; i++) split2(e[i], ph[i], pl[i]);
    *(uint4*)(g_wh + base) = *(uint4*)ph;
    *(uint4*)(g_wl + base) = *(uint4*)pl;
}

__global__ void zero_kernel() {
    int i = blockIdx.x * blockDim.x + threadIdx.x;
    if (i < GV_) { g_probsum[i] = 0.0f; g_counts[i] = 0u; }
}

// ---------------------------------------------------------------------------
// GEMM (fused X-split): logits = X @ W^T + bias, fp16x2 3-term mma.sync.
// CTA: 128(M) x 128(N), K-chunks of 32, double-buffered cp.async.
// smem/CTA = 92KB -> 2 CTAs/SM. (unchanged — at HMMA steady state)
// ---------------------------------------------------------------------------
#define ROWB   80                       // fp16 plane row stride bytes (64B data)
#define BPL    (128 * ROWB)             // 10240: one B plane tile
#define BSTG   (2 * BPL)                // 20480: per-stage B (h + l planes)
#define OFF_B  0                        // 2 stages: 40960
#define ASF    (128 * 128)              // 16384: fp32 A staging (128 rows x 128B)
#define OFF_AS 40960                    // 2 stages: 32768
#define OFF_AH 73728                    // Ah fp16 plane (single buffer)
#define OFF_AL 83968                    // Al fp16 plane (single buffer)
#define GSMEM  94208                    // 92KB

#define NCHUNK 32                       // 1024 / 32

__device__ __forceinline__ void load_stage(uint32_t smb, const float* __restrict__ X,
                                           int m0, int n0, int k0, int st, int tid) {
    // B: 2 planes x 128 rows x 4 segs(16B) = 1024 copies
#pragma unroll
    for (int i = 0; i < 4; i++) {
        const int e     = i * 256 + tid;        // 0..1023
        const int plane = e >> 9;               // 0..1
        const int rem   = e & 511;
        const int row   = rem >> 2;
        const int seg   = rem & 3;
        const uint32_t dst = smb + OFF_B + st * BSTG + plane * BPL +
                             (uint32_t)row * ROWB + seg * 16;
        const size_t src = (size_t)(n0 + row) * FIN_ + k0 + seg * 8;
        cpasync16(dst, (plane ? g_wl : g_wh) + src);
    }
    // A fp32 staging: 128 rows x 8 segs(16B) = 1024 copies (same e-mapping as convert)
#pragma unroll
    for (int i = 0; i < 4; i++) {
        const int e   = i * 256 + tid;
        const int row = e >> 3;
        const int seg = e & 7;
        const uint32_t dst = smb + OFF_AS + st * ASF + (uint32_t)row * 128 + seg * 16;
        cpasync16(dst, X + (size_t)(m0 + row) * FIN_ + k0 + seg * 4);
    }
}

__global__ __launch_bounds__(256, 2) void gemm_kernel(const float* __restrict__ X,
                                                      const float* __restrict__ bias) {
    extern __shared__ char sm[];
    const uint32_t smb = smem_u32(sm);
    const int tid = threadIdx.x;
    const int wid = tid >> 5;
    const int lid = tid & 31;
    const int wm  = wid & 1;        // 0..1
    const int wn  = wid >> 1;       // 0..3
    const int n0  = blockIdx.x * 128;
    const int m0  = blockIdx.y * 128;

    float acc[4][4][4];
#pragma unroll
    for (int a = 0; a < 4; a++)
#pragma unroll
        for (int b = 0; b < 4; b++)
#pragma unroll
            for (int c = 0; c < 4; c++) acc[a][b][c] = 0.0f;

    // lane-constant ldmatrix offsets (identical operand mapping to R8)
    const int rowA  = (lid & 7) + ((lid >> 3) & 1) * 8;
    const int kselA = (lid >> 4) * 8;
    const int nB    = (lid >> 4) * 8 + (lid & 7);
    const int kselB = ((lid >> 3) & 1) * 8;
    const uint32_t aoff = (uint32_t)(wm * 64 + rowA) * ROWB + kselA * 2;
    const uint32_t boff = (uint32_t)(wn * 32 + nB) * ROWB + kselB * 2;

    load_stage(smb, X, m0, n0, 0, 0, tid);
    CP_COMMIT();

    for (int c = 0; c < NCHUNK; c++) {
        const int nk = c + 1;
        if (nk < NCHUNK) {
            load_stage(smb, X, m0, n0, nk * 32, nk & 1, tid);
            CP_COMMIT();
            CP_WAIT1();          // chunk c's group complete; next may fly
        } else {
            CP_WAIT0();          // last chunk: full drain
        }

        // Convert own staged fp32 A bytes -> fp16 planes (no barrier needed:
        // each thread reads exactly the bytes its own cp.async wrote).
#pragma unroll
        for (int i = 0; i < 4; i++) {
            const int e   = i * 256 + tid;
            const int row = e >> 3;
            const int seg = e & 7;
            const float4 v = *(const float4*)(sm + OFF_AS + (c & 1) * ASF +
                                              row * 128 + seg * 16);
            __half ph[4], pl[4];
            split2(v.x, ph[0], pl[0]); split2(v.y, ph[1], pl[1]);
            split2(v.z, ph[2], pl[2]); split2(v.w, ph[3], pl[3]);
            const uint32_t d = (uint32_t)row * ROWB + seg * 8;
            *(uint2*)(sm + OFF_AH + d) = *(uint2*)ph;
            *(uint2*)(sm + OFF_AL + d) = *(uint2*)pl;
        }
        __syncthreads();

        const uint32_t sb = smb + OFF_B + (c & 1) * BSTG;
#pragma unroll
        for (int ks = 0; ks < 2; ks++) {
            uint32_t bh[2][4], bl[2][4];
#pragma unroll
            for (int nt2 = 0; nt2 < 2; nt2++) {
                const uint32_t bd = sb + boff + nt2 * (16 * ROWB) + ks * 32;
                LDM4(bh[nt2], bd);
                LDM4(bl[nt2], bd + BPL);
            }
#pragma unroll
            for (int mt = 0; mt < 4; mt++) {
                uint32_t ah[4], al[4];
                const uint32_t ad = smb + OFF_AH + aoff + mt * (16 * ROWB) + ks * 32;
                LDM4(ah, ad);
                LDM4(al, ad + (OFF_AL - OFF_AH));
#pragma unroll
                for (int nt = 0; nt < 4; nt++) {
                    const uint32_t bh0 = bh[nt >> 1][(nt & 1) * 2];
                    const uint32_t bh1 = bh[nt >> 1][(nt & 1) * 2 + 1];
                    const uint32_t bl0 = bl[nt >> 1][(nt & 1) * 2];
                    const uint32_t bl1 = bl[nt >> 1][(nt & 1) * 2 + 1];
                    MMA16816(acc[mt][nt], ah, bh0, bh1);
                    MMA16816(acc[mt][nt], ah, bl0, bl1);
                    MMA16816(acc[mt][nt], al, bh0, bh1);
                }
            }
        }
        __syncthreads();   // MMAs done before next chunk's convert/cp.async overwrite
    }

    // write logits (+bias)
    const int g   = lid >> 2;
    const int tig = lid & 3;
#pragma unroll
    for (int nt = 0; nt < 4; nt++) {
        const int col = n0 + wn * 32 + nt * 8 + tig * 2;
        const float b0 = __ldg(bias + col);
        const float b1 = __ldg(bias + col + 1);
#pragma unroll
        for (int mt = 0; mt < 4; mt++) {
            const int r0 = m0 + wm * 64 + mt * 16 + g;
            float2 v0 = make_float2(acc[mt][nt][0] + b0, acc[mt][nt][1] + b1);
            float2 v1 = make_float2(acc[mt][nt][2] + b0, acc[mt][nt][3] + b1);
            *(float2*)&g_logits[(size_t)r0 * GV_ + col]       = v0;
            *(float2*)&g_logits[(size_t)(r0 + 8) * GV_ + col] = v1;
        }
    }
}

// ---------------------------------------------------------------------------
// Epilogue: 1 warp per 2 (row, group) items, interleaved register streams.
// The two rows' shuffle-reduction chains are independent -> 2x ILP across
// the dominant latency chains. Near ties re-decided with round-2 numerics.
// ---------------------------------------------------------------------------
__device__ __forceinline__ bool better(float v, int i, float v2, int i2) {
    return (v > v2) || (v == v2 && i < i2);
}

__device__ __noinline__ float seq_dot(const float* __restrict__ xr,
                                      const float* __restrict__ wr) {
    float s = 0.0f;
#pragma unroll 8
    for (int k = 0; k < FIN_; k++) s = fmaf(__ldg(xr + k), __ldg(wr + k), s);
    return s;
}

__global__ __launch_bounds__(256) void epi_kernel(const float* __restrict__ X,
                                                  const float* __restrict__ W,
                                                  const float* __restrict__ bias,
                                                  const float* __restrict__ GMB,
                                                  const float* __restrict__ CB,
                                                  float* __restrict__ out) {
    __shared__ float        sprob[GV_];
    __shared__ unsigned int scnt[GV_];
    const int tid = threadIdx.x;
    for (int i = tid; i < GV_; i += 256) { sprob[i] = 0.0f; scnt[i] = 0u; }
    __syncthreads();

    const int warp = tid >> 5;
    const int lane = tid & 31;
    const int g    = warp & 1;
    const int slot = warp >> 1;
    const int rbase = blockIdx.x * 64 + slot;
    const int nbase = g * NV_;

    float pacc[10];
#pragma unroll
    for (int j = 0; j < 10; j++) pacc[j] = 0.0f;

    for (int p = 0; p < 8; p++) {
        int row[2];
        row[0] = rbase + (2 * p) * 4;
        row[1] = rbase + (2 * p + 1) * 4;

        const float* lp[2];
        const float* gp[2];
        float lv[2][10], gv[2][10];
#pragma unroll
        for (int r = 0; r < 2; r++) {
            lp[r] = g_logits + (size_t)row[r] * GV_ + nbase;
            gp[r] = GMB     + (size_t)row[r] * GV_ + nbase;
#pragma unroll
            for (int j = 0; j < 10; j++) lv[r][j] = lp[r][j * 32 + lane];
#pragma unroll
            for (int j = 0; j < 10; j++) gv[r][j] = gp[r][j * 32 + lane];
        }

        // ---- raw argmax (both rows, interleaved butterfly) ----
        float bm[2]; int bi[2];
#pragma unroll
        for (int r = 0; r < 2; r++) {
            bm[r] = lv[r][0]; bi[r] = lane;
#pragma unroll
            for (int j = 1; j < 10; j++)
                if (lv[r][j] > bm[r]) { bm[r] = lv[r][j]; bi[r] = j * 32 + lane; }
        }
#pragma unroll
        for (int off = 16; off > 0; off >>= 1) {
#pragma unroll
            for (int r = 0; r < 2; r++) {
                const float om = __shfl_xor_sync(0xffffffffu, bm[r], off);
                const int   oi = __shfl_xor_sync(0xffffffffu, bi[r], off);
                if (om > bm[r] || (om == bm[r] && oi < bi[r])) { bm[r] = om; bi[r] = oi; }
            }
        }
        if (lane == 0) {
            atomicAdd(&scnt[nbase + bi[0]], 1u);
            atomicAdd(&scnt[nbase + bi[1]], 1u);
        }

        // ---- softmax accumulate (both rows) ----
        float ev[2][10];
        float s[2] = {0.0f, 0.0f};
#pragma unroll
        for (int r = 0; r < 2; r++)
#pragma unroll
            for (int j = 0; j < 10; j++) { ev[r][j] = __expf(lv[r][j] - bm[r]); s[r] += ev[r][j]; }
#pragma unroll
        for (int off = 16; off > 0; off >>= 1) {
#pragma unroll
            for (int r = 0; r < 2; r++) s[r] += __shfl_xor_sync(0xffffffffu, s[r], off);
        }
        // accumulate row0 then row1 (original sequential it-order preserved)
#pragma unroll
        for (int r = 0; r < 2; r++) {
            const float inv = 1.0f / s[r];
#pragma unroll
            for (int j = 0; j < 10; j++) pacc[j] += ev[r][j] * inv;
        }

        // ---- gumbel top-2 (both rows, interleaved butterfly) ----
        float m1[2], m2[2]; int i1[2], i2[2];
#pragma unroll
        for (int r = 0; r < 2; r++) {
            m1[r] = -1e30f; m2[r] = -1e30f; i1[r] = 0x7fffffff; i2[r] = 0x7fffffff;
#pragma unroll
            for (int j = 0; j < 10; j++) {
                const float t = lv[r][j] + gv[r][j];
                const int idx = j * 32 + lane;
                if (t > m1[r]) { m2[r] = m1[r]; i2[r] = i1[r]; m1[r] = t; i1[r] = idx; }
                else if (t > m2[r]) { m2[r] = t; i2[r] = idx; }
            }
        }
#pragma unroll
        for (int off = 16; off > 0; off >>= 1) {
#pragma unroll
            for (int r = 0; r < 2; r++) {
                const float om1 = __shfl_xor_sync(0xffffffffu, m1[r], off);
                const int   oi1 = __shfl_xor_sync(0xffffffffu, i1[r], off);
                const float om2 = __shfl_xor_sync(0xffffffffu, m2[r], off);
                const int   oi2 = __shfl_xor_sync(0xffffffffu, i2[r], off);
                if (better(om1, oi1, m1[r], i1[r])) {
                    if (better(m1[r], i1[r], om2, oi2)) { m2[r] = m1[r]; i2[r] = i1[r]; }
                    else                                { m2[r] = om2;  i2[r] = oi2; }
                    m1[r] = om1; i1[r] = oi1;
                } else if (better(om1, oi1, m2[r], i2[r])) {
                    m2[r] = om1; i2[r] = oi1;
                }
            }
        }

        // ---- rescue + q gather per row ----
#pragma unroll
        for (int r = 0; r < 2; r++) {
            int winner = i1[r];
            if (m1[r] - m2[r] < TAU_RESCUE) {
                int w_local = 0;
                if (lane == 0) {
                    const float* xr = X + (size_t)row[r] * FIN_;
                    const float e1 = seq_dot(xr, W + (size_t)(nbase + i1[r]) * FIN_)
                                     + __ldg(bias + nbase + i1[r]) + __ldg(gp[r] + i1[r]);
                    const float e2 = seq_dot(xr, W + (size_t)(nbase + i2[r]) * FIN_)
                                     + __ldg(bias + nbase + i2[r]) + __ldg(gp[r] + i2[r]);
                    w_local = better(e1, i1[r], e2, i2[r]) ? i1[r] : i2[r];
                }
                winner = __shfl_sync(0xffffffffu, w_local, 0);
            }
            const float4* src = (const float4*)(CB + (size_t)(nbase + winner) * VD_);
            float4*       dst = (float4*)(out + ((size_t)row[r] * 2 + g) * VD_);
            dst[lane] = src[lane];
        }
    }

    // merge per-warp prob accumulators -> global
#pragma unroll
    for (int j = 0; j < 10; j++) atomicAdd(&sprob[nbase + j * 32 + lane], pacc[j]);
    __syncthreads();
    for (int i = tid; i < GV_; i += 256) {
        atomicAdd(&g_probsum[i], sprob[i]);
        atomicAdd(&g_counts[i], scnt[i]);
    }
}

// ---------------------------------------------------------------------------
// Perplexity scalars. out layout: [q | code_ppl | prob_ppl]
// ---------------------------------------------------------------------------
__global__ void fin_kernel(float* __restrict__ out) {
    const int lane = threadIdx.x;
    const float invBT = 1.0f / (float)BT_;
    float Hs[2], Hc[2];
#pragma unroll
    for (int g = 0; g < 2; g++) {
        float hs = 0.0f, hc = 0.0f;
        for (int j = 0; j < 10; j++) {
            const int v = g * NV_ + j * 32 + lane;
            const float p = g_probsum[v] * invBT;
            const float c = (float)g_counts[v] * invBT;
            hs += p * logf(p + 1e-7f);
            hc += c * logf(c + 1e-7f);
        }
#pragma unroll
        for (int off = 16; off > 0; off >>= 1) {
            hs += __shfl_xor_sync(0xffffffffu, hs, off);
            hc += __shfl_xor_sync(0xffffffffu, hc, off);
        }
        Hs[g] = hs; Hc[g] = hc;
    }
    if (lane == 0) {
        out[QELEMS]     = expf(-Hc[0]) + expf(-Hc[1]);
        out[QELEMS + 1] = expf(-Hs[0]) + expf(-Hs[1]);
    }
}

// ---------------------------------------------------------------------------
// Launch
// inputs: 0=x, 1=proj_w, 2=proj_b, 3=codebook, 4=gumbel ; output f32
// ---------------------------------------------------------------------------
extern "C" void kernel_launch(void* const* d_in, const int* in_sizes, int n_in,
                              void* d_out, int out_size) {
    (void)in_sizes; (void)n_in; (void)out_size;
    const float* X    = (const float*)d_in[0];
    const float* W    = (const float*)d_in[1];
    const float* bias = (const float*)d_in[2];
    const float* CB   = (const float*)d_in[3];
    const float* GMB  = (const float*)d_in[4];
    float* out = (float*)d_out;

    cudaFuncSetAttribute(gemm_kernel, cudaFuncAttributeMaxDynamicSharedMemorySize, GSMEM);

    zero_kernel<<<3, 256>>>();
    wsplit_kernel<<<320, 256>>>(W);
    dim3 ggrid(5, 500);   // x: N tiles (640/128), y: M tiles (64000/128)
    gemm_kernel<<<ggrid, 256, GSMEM>>>(X, bias);
    epi_kernel<<<1000, 256>>>(X, W, bias, GMB, CB, out);
    fin_kernel<<<1, 32>>>(out);
}

// round 16
// speedup vs baseline: 1.0523x; 1.0523x over previous
#include <cuda_runtime.h>
#include <cuda_fp16.h>
#include <cstdint>

// Problem constants
#define BT_    64000          // B*T
#define FIN_   1024
#define GV_    640            // GROUPS*NUM_VARS
#define NV_    320
#define VD_    128            // VAR_DIM
#define QELEMS (BT_ * 256)    // q output elements

#define TAU_RESCUE 0.02f

// ---------------------------------------------------------------------------
// Device scratch (no cudaMalloc allowed)
// ---------------------------------------------------------------------------
__device__ __align__(16) __half g_wh[(size_t)GV_ * FIN_];
__device__ __align__(16) __half g_wl[(size_t)GV_ * FIN_];
__device__ __align__(16) float  g_logits[(size_t)BT_ * GV_];
__device__ float        g_probsum[GV_];
__device__ unsigned int g_counts[GV_];

// ---------------------------------------------------------------------------
// PTX helpers (base-target only: cp.async / ldmatrix / mma.sync)
// ---------------------------------------------------------------------------
__device__ __forceinline__ uint32_t smem_u32(const void* p) {
    uint32_t a;
    asm("{ .reg .u64 t; cvta.to.shared.u64 t, %1; cvt.u32.u64 %0, t; }" : "=r"(a) : "l"(p));
    return a;
}
__device__ __forceinline__ void cpasync16(uint32_t dst, const void* src) {
    asm volatile("cp.async.cg.shared.global [%0], [%1], 16;" :: "r"(dst), "l"(src));
}
#define CP_COMMIT() asm volatile("cp.async.commit_group;")
#define CP_WAIT1()  asm volatile("cp.async.wait_group 1;")
#define CP_WAIT0()  asm volatile("cp.async.wait_group 0;")

#define LDM4(r, addr) \
    asm volatile("ldmatrix.sync.aligned.m8n8.x4.shared.b16 {%0,%1,%2,%3}, [%4];" \
                 : "=r"((r)[0]), "=r"((r)[1]), "=r"((r)[2]), "=r"((r)[3]) : "r"(addr))

#define MMA16816(d, a, b0r, b1r) \
    asm volatile("mma.sync.aligned.m16n8k16.row.col.f32.f16.f16.f32 " \
                 "{%0,%1,%2,%3},{%4,%5,%6,%7},{%8,%9},{%0,%1,%2,%3};" \
                 : "+f"((d)[0]), "+f"((d)[1]), "+f"((d)[2]), "+f"((d)[3]) \
                 : "r"((a)[0]), "r"((a)[1]), "r"((a)[2]), "r"((a)[3]), "r"(b0r), "r"(b1r))

// ---------------------------------------------------------------------------
// fp16x2 split
// ---------------------------------------------------------------------------
__device__ __forceinline__ void split2(float x, __half& h, __half& l) {
    h = __float2half(x);
    l = __float2half(x - __half2float(h));
}

__global__ __launch_bounds__(256) void wsplit_kernel(const float* __restrict__ W) {
    const size_t base = ((size_t)blockIdx.x * 256 + threadIdx.x) * 8;
    const float4 v0 = *(const float4*)(W + base);
    const float4 v1 = *(const float4*)(W + base + 4);
    const float e[8] = {v0.x, v0.y, v0.z, v0.w, v1.x, v1.y, v1.z, v1.w};
    __half ph[8], pl[8];
#pragma unroll
    for (int i = 0; i < 8; i++) split2(e[i], ph[i], pl[i]);
    *(uint4*)(g_wh + base) = *(uint4*)ph;
    *(uint4*)(g_wl + base) = *(uint4*)pl;
}

__global__ void zero_kernel() {
    int i = blockIdx.x * blockDim.x + threadIdx.x;
    if (i < GV_) { g_probsum[i] = 0.0f; g_counts[i] = 0u; }
}

// ---------------------------------------------------------------------------
// GEMM (fused X-split): logits = X @ W^T + bias, fp16x2 3-term mma.sync.
// CTA: 128(M) x 128(N), K-chunks of 32, double-buffered cp.async.
// smem/CTA = 92KB -> 2 CTAs/SM. (unchanged — at HMMA steady state)
// ---------------------------------------------------------------------------
#define ROWB   80                       // fp16 plane row stride bytes (64B data)
#define BPL    (128 * ROWB)             // 10240: one B plane tile
#define BSTG   (2 * BPL)                // 20480: per-stage B (h + l planes)
#define OFF_B  0                        // 2 stages: 40960
#define ASF    (128 * 128)              // 16384: fp32 A staging (128 rows x 128B)
#define OFF_AS 40960                    // 2 stages: 32768
#define OFF_AH 73728                    // Ah fp16 plane (single buffer)
#define OFF_AL 83968                    // Al fp16 plane (single buffer)
#define GSMEM  94208                    // 92KB

#define NCHUNK 32                       // 1024 / 32

__device__ __forceinline__ void load_stage(uint32_t smb, const float* __restrict__ X,
                                           int m0, int n0, int k0, int st, int tid) {
    // B: 2 planes x 128 rows x 4 segs(16B) = 1024 copies
#pragma unroll
    for (int i = 0; i < 4; i++) {
        const int e     = i * 256 + tid;        // 0..1023
        const int plane = e >> 9;               // 0..1
        const int rem   = e & 511;
        const int row   = rem >> 2;
        const int seg   = rem & 3;
        const uint32_t dst = smb + OFF_B + st * BSTG + plane * BPL +
                             (uint32_t)row * ROWB + seg * 16;
        const size_t src = (size_t)(n0 + row) * FIN_ + k0 + seg * 8;
        cpasync16(dst, (plane ? g_wl : g_wh) + src);
    }
    // A fp32 staging: 128 rows x 8 segs(16B) = 1024 copies (same e-mapping as convert)
#pragma unroll
    for (int i = 0; i < 4; i++) {
        const int e   = i * 256 + tid;
        const int row = e >> 3;
        const int seg = e & 7;
        const uint32_t dst = smb + OFF_AS + st * ASF + (uint32_t)row * 128 + seg * 16;
        cpasync16(dst, X + (size_t)(m0 + row) * FIN_ + k0 + seg * 4);
    }
}

__global__ __launch_bounds__(256, 2) void gemm_kernel(const float* __restrict__ X,
                                                      const float* __restrict__ bias) {
    extern __shared__ char sm[];
    const uint32_t smb = smem_u32(sm);
    const int tid = threadIdx.x;
    const int wid = tid >> 5;
    const int lid = tid & 31;
    const int wm  = wid & 1;        // 0..1
    const int wn  = wid >> 1;       // 0..3
    const int n0  = blockIdx.x * 128;
    const int m0  = blockIdx.y * 128;

    float acc[4][4][4];
#pragma unroll
    for (int a = 0; a < 4; a++)
#pragma unroll
        for (int b = 0; b < 4; b++)
#pragma unroll
            for (int c = 0; c < 4; c++) acc[a][b][c] = 0.0f;

    // lane-constant ldmatrix offsets (identical operand mapping to R8)
    const int rowA  = (lid & 7) + ((lid >> 3) & 1) * 8;
    const int kselA = (lid >> 4) * 8;
    const int nB    = (lid >> 4) * 8 + (lid & 7);
    const int kselB = ((lid >> 3) & 1) * 8;
    const uint32_t aoff = (uint32_t)(wm * 64 + rowA) * ROWB + kselA * 2;
    const uint32_t boff = (uint32_t)(wn * 32 + nB) * ROWB + kselB * 2;

    load_stage(smb, X, m0, n0, 0, 0, tid);
    CP_COMMIT();

    for (int c = 0; c < NCHUNK; c++) {
        const int nk = c + 1;
        if (nk < NCHUNK) {
            load_stage(smb, X, m0, n0, nk * 32, nk & 1, tid);
            CP_COMMIT();
            CP_WAIT1();          // chunk c's group complete; next may fly
        } else {
            CP_WAIT0();          // last chunk: full drain
        }

        // Convert own staged fp32 A bytes -> fp16 planes (no barrier needed:
        // each thread reads exactly the bytes its own cp.async wrote).
#pragma unroll
        for (int i = 0; i < 4; i++) {
            const int e   = i * 256 + tid;
            const int row = e >> 3;
            const int seg = e & 7;
            const float4 v = *(const float4*)(sm + OFF_AS + (c & 1) * ASF +
                                              row * 128 + seg * 16);
            __half ph[4], pl[4];
            split2(v.x, ph[0], pl[0]); split2(v.y, ph[1], pl[1]);
            split2(v.z, ph[2], pl[2]); split2(v.w, ph[3], pl[3]);
            const uint32_t d = (uint32_t)row * ROWB + seg * 8;
            *(uint2*)(sm + OFF_AH + d) = *(uint2*)ph;
            *(uint2*)(sm + OFF_AL + d) = *(uint2*)pl;
        }
        __syncthreads();

        const uint32_t sb = smb + OFF_B + (c & 1) * BSTG;
#pragma unroll
        for (int ks = 0; ks < 2; ks++) {
            uint32_t bh[2][4], bl[2][4];
#pragma unroll
            for (int nt2 = 0; nt2 < 2; nt2++) {
                const uint32_t bd = sb + boff + nt2 * (16 * ROWB) + ks * 32;
                LDM4(bh[nt2], bd);
                LDM4(bl[nt2], bd + BPL);
            }
#pragma unroll
            for (int mt = 0; mt < 4; mt++) {
                uint32_t ah[4], al[4];
                const uint32_t ad = smb + OFF_AH + aoff + mt * (16 * ROWB) + ks * 32;
                LDM4(ah, ad);
                LDM4(al, ad + (OFF_AL - OFF_AH));
#pragma unroll
                for (int nt = 0; nt < 4; nt++) {
                    const uint32_t bh0 = bh[nt >> 1][(nt & 1) * 2];
                    const uint32_t bh1 = bh[nt >> 1][(nt & 1) * 2 + 1];
                    const uint32_t bl0 = bl[nt >> 1][(nt & 1) * 2];
                    const uint32_t bl1 = bl[nt >> 1][(nt & 1) * 2 + 1];
                    MMA16816(acc[mt][nt], ah, bh0, bh1);
                    MMA16816(acc[mt][nt], ah, bl0, bl1);
                    MMA16816(acc[mt][nt], al, bh0, bh1);
                }
            }
        }
        __syncthreads();   // MMAs done before next chunk's convert/cp.async overwrite
    }

    // write logits (+bias)
    const int g   = lid >> 2;
    const int tig = lid & 3;
#pragma unroll
    for (int nt = 0; nt < 4; nt++) {
        const int col = n0 + wn * 32 + nt * 8 + tig * 2;
        const float b0 = __ldg(bias + col);
        const float b1 = __ldg(bias + col + 1);
#pragma unroll
        for (int mt = 0; mt < 4; mt++) {
            const int r0 = m0 + wm * 64 + mt * 16 + g;
            float2 v0 = make_float2(acc[mt][nt][0] + b0, acc[mt][nt][1] + b1);
            float2 v1 = make_float2(acc[mt][nt][2] + b0, acc[mt][nt][3] + b1);
            *(float2*)&g_logits[(size_t)r0 * GV_ + col]       = v0;
            *(float2*)&g_logits[(size_t)(r0 + 8) * GV_ + col] = v1;
        }
    }
}

// ---------------------------------------------------------------------------
// Epilogue: 1 warp per (row, group). Low-register variant: probs accumulated
// straight into shared sprob (conflict-free lanes), exp recomputed instead of
// cached, no persistent pacc/ev arrays. __launch_bounds__(256,5) for occupancy.
// Near ties re-decided with round-2 numerics (sequential fp32 fmaf dot).
// ---------------------------------------------------------------------------
__device__ __forceinline__ bool better(float v, int i, float v2, int i2) {
    return (v > v2) || (v == v2 && i < i2);
}

__device__ __noinline__ float seq_dot(const float* __restrict__ xr,
                                      const float* __restrict__ wr) {
    float s = 0.0f;
#pragma unroll 8
    for (int k = 0; k < FIN_; k++) s = fmaf(__ldg(xr + k), __ldg(wr + k), s);
    return s;
}

__global__ __launch_bounds__(256, 5) void epi_kernel(const float* __restrict__ X,
                                                     const float* __restrict__ W,
                                                     const float* __restrict__ bias,
                                                     const float* __restrict__ GMB,
                                                     const float* __restrict__ CB,
                                                     float* __restrict__ out) {
    __shared__ float        sprob[GV_];
    __shared__ unsigned int scnt[GV_];
    const int tid = threadIdx.x;
    for (int i = tid; i < GV_; i += 256) { sprob[i] = 0.0f; scnt[i] = 0u; }
    __syncthreads();

    const int warp = tid >> 5;
    const int lane = tid & 31;
    const int g    = warp & 1;
    const int slot = warp >> 1;
    const int rbase = blockIdx.x * 64 + slot;
    const int nbase = g * NV_;

    for (int it = 0; it < 16; it++) {
        const int row = rbase + it * 4;
        const float* lp = g_logits + (size_t)row * GV_ + nbase;
        const float* gp = GMB     + (size_t)row * GV_ + nbase;

        // ---- issue all independent loads first ----
        float lv[10], gv[10];
#pragma unroll
        for (int j = 0; j < 10; j++) lv[j] = lp[j * 32 + lane];
#pragma unroll
        for (int j = 0; j < 10; j++) gv[j] = gp[j * 32 + lane];

        // ---- raw argmax ----
        float bm = lv[0];
        int   bi = lane;
#pragma unroll
        for (int j = 1; j < 10; j++)
            if (lv[j] > bm) { bm = lv[j]; bi = j * 32 + lane; }
#pragma unroll
        for (int off = 16; off > 0; off >>= 1) {
            const float om = __shfl_xor_sync(0xffffffffu, bm, off);
            const int   oi = __shfl_xor_sync(0xffffffffu, bi, off);
            if (om > bm || (om == bm && oi < bi)) { bm = om; bi = oi; }
        }
        if (lane == 0) atomicAdd(&scnt[nbase + bi], 1u);

        // ---- softmax: sum, then accumulate directly into shared ----
        float s = 0.0f;
#pragma unroll
        for (int j = 0; j < 10; j++) s += __expf(lv[j] - bm);
#pragma unroll
        for (int off = 16; off > 0; off >>= 1) s += __shfl_xor_sync(0xffffffffu, s, off);
        const float inv = 1.0f / s;
#pragma unroll
        for (int j = 0; j < 10; j++)
            atomicAdd(&sprob[nbase + j * 32 + lane], __expf(lv[j] - bm) * inv);

        // ---- gumbel top-2 ----
        float m1 = -1e30f, m2 = -1e30f;
        int   i1 = 0x7fffffff, i2 = 0x7fffffff;
#pragma unroll
        for (int j = 0; j < 10; j++) {
            const float t = lv[j] + gv[j];
            const int idx = j * 32 + lane;
            if (t > m1) { m2 = m1; i2 = i1; m1 = t; i1 = idx; }
            else if (t > m2) { m2 = t; i2 = idx; }
        }
#pragma unroll
        for (int off = 16; off > 0; off >>= 1) {
            const float om1 = __shfl_xor_sync(0xffffffffu, m1, off);
            const int   oi1 = __shfl_xor_sync(0xffffffffu, i1, off);
            const float om2 = __shfl_xor_sync(0xffffffffu, m2, off);
            const int   oi2 = __shfl_xor_sync(0xffffffffu, i2, off);
            if (better(om1, oi1, m1, i1)) {
                if (better(m1, i1, om2, oi2)) { m2 = m1; i2 = i1; }
                else                          { m2 = om2; i2 = oi2; }
                m1 = om1; i1 = oi1;
            } else if (better(om1, oi1, m2, i2)) {
                m2 = om1; i2 = oi1;
            }
        }

        int winner = i1;
        if (m1 - m2 < TAU_RESCUE) {
            int w_local = 0;
            if (lane == 0) {
                const float* xr = X + (size_t)row * FIN_;
                const float e1 = seq_dot(xr, W + (size_t)(nbase + i1) * FIN_)
                                 + __ldg(bias + nbase + i1) + __ldg(gp + i1);
                const float e2 = seq_dot(xr, W + (size_t)(nbase + i2) * FIN_)
                                 + __ldg(bias + nbase + i2) + __ldg(gp + i2);
                w_local = better(e1, i1, e2, i2) ? i1 : i2;
            }
            winner = __shfl_sync(0xffffffffu, w_local, 0);
        }

        // q gather: 32 lanes x 16B = full 512B codebook row
        const float4* src = (const float4*)(CB + (size_t)(nbase + winner) * VD_);
        float4*       dst = (float4*)(out + ((size_t)row * 2 + g) * VD_);
        dst[lane] = src[lane];
    }

    // merge shared accumulators -> global
    __syncthreads();
    for (int i = tid; i < GV_; i += 256) {
        atomicAdd(&g_probsum[i], sprob[i]);
        atomicAdd(&g_counts[i], scnt[i]);
    }
}

// ---------------------------------------------------------------------------
// Perplexity scalars. out layout: [q | code_ppl | prob_ppl]
// ---------------------------------------------------------------------------
__global__ void fin_kernel(float* __restrict__ out) {
    const int lane = threadIdx.x;
    const float invBT = 1.0f / (float)BT_;
    float Hs[2], Hc[2];
#pragma unroll
    for (int g = 0; g < 2; g++) {
        float hs = 0.0f, hc = 0.0f;
        for (int j = 0; j < 10; j++) {
            const int v = g * NV_ + j * 32 + lane;
            const float p = g_probsum[v] * invBT;
            const float c = (float)g_counts[v] * invBT;
            hs += p * logf(p + 1e-7f);
            hc += c * logf(c + 1e-7f);
        }
#pragma unroll
        for (int off = 16; off > 0; off >>= 1) {
            hs += __shfl_xor_sync(0xffffffffu, hs, off);
            hc += __shfl_xor_sync(0xffffffffu, hc, off);
        }
        Hs[g] = hs; Hc[g] = hc;
    }
    if (lane == 0) {
        out[QELEMS]     = expf(-Hc[0]) + expf(-Hc[1]);
        out[QELEMS + 1] = expf(-Hs[0]) + expf(-Hs[1]);
    }
}

// ---------------------------------------------------------------------------
// Launch
// inputs: 0=x, 1=proj_w, 2=proj_b, 3=codebook, 4=gumbel ; output f32
// ---------------------------------------------------------------------------
extern "C" void kernel_launch(void* const* d_in, const int* in_sizes, int n_in,
                              void* d_out, int out_size) {
    (void)in_sizes; (void)n_in; (void)out_size;
    const float* X    = (const float*)d_in[0];
    const float* W    = (const float*)d_in[1];
    const float* bias = (const float*)d_in[2];
    const float* CB   = (const float*)d_in[3];
    const float* GMB  = (const float*)d_in[4];
    float* out = (float*)d_out;

    cudaFuncSetAttribute(gemm_kernel, cudaFuncAttributeMaxDynamicSharedMemorySize, GSMEM);

    zero_kernel<<<3, 256>>>();
    wsplit_kernel<<<320, 256>>>(W);
    dim3 ggrid(5, 500);   // x: N tiles (640/128), y: M tiles (64000/128)
    gemm_kernel<<<ggrid, 256, GSMEM>>>(X, bias);
    epi_kernel<<<1000, 256>>>(X, W, bias, GMB, CB, out);
    fin_kernel<<<1, 32>>>(out);
}